// round 5
// baseline (speedup 1.0000x reference)
#include <cuda_runtime.h>
#include <cuda_bf16.h>

// Problem constants
#define B_    8
#define C_IN  64
#define C_OUT 128
#define H_IN  256
#define W_IN  256
#define H_OUT 128
#define W_OUT 128
#define M_MAP 800000
#define V_SEG 200000
#define N_PTS 50000

#define CICHUNK 8      // input-channel chunk held in smem
#define WOB 64         // wo tile per block (8 warps x 8 wo each)
#define XCOLS 132      // 129 valid cols padded (in dup-pair elements)

// Scratch: conv output in NHWC-flat layout [B*H_OUT*W_OUT, C_OUT] (67 MB)
__device__ __align__(256) float g_y[(size_t)B_ * H_OUT * W_OUT * C_OUT];
// Transposed weights: [ci][k][co] (294 KB) for vectorized smem fills
__device__ __align__(256) float g_wT[C_IN * 9 * C_OUT];

// ---------------------------------------------------------------------------
// Packed fp32x2 helpers (Blackwell FFMA2 — only reachable via PTX)
// ---------------------------------------------------------------------------
__device__ __forceinline__ unsigned long long bcast2(float x) {
    unsigned long long r;
    asm("mov.b64 %0, {%1, %1};" : "=l"(r) : "f"(x));
    return r;
}
__device__ __forceinline__ void fma2(unsigned long long& d,
                                     unsigned long long a,
                                     unsigned long long b) {
    asm("fma.rn.f32x2 %0, %1, %2, %0;" : "+l"(d) : "l"(a), "l"(b));
}
__device__ __forceinline__ void unpack2(unsigned long long v, float& lo, float& hi) {
    asm("mov.b64 {%0, %1}, %2;" : "=f"(lo), "=f"(hi) : "l"(v));
}

// ---------------------------------------------------------------------------
// Kernel 0: transpose weights (C_OUT,C_IN,3,3) -> [ci][k][co]
// ---------------------------------------------------------------------------
__global__ void wt_transpose_kernel(const float* __restrict__ w) {
    int idx = blockIdx.x * blockDim.x + threadIdx.x;
    int total = C_IN * 9 * C_OUT;
    if (idx >= total) return;
    int co = idx % C_OUT;
    int k  = (idx / C_OUT) % 9;
    int ci = idx / (9 * C_OUT);
    g_wT[idx] = w[(co * C_IN + ci) * 9 + k];
}

// ---------------------------------------------------------------------------
// Kernel 1: 3x3 stride-2 pad-1 conv + bias + ReLU, NCHW in -> NHWC-flat out.
// Block: 256 threads computes (1 b, 1 ho, 64 wo, 128 co).
// Warp w handles wo [w*8, w*8+8); lane l handles co [l*4, l*4+4).
// Inner math: packed fp32x2 FMA (FFMA2). x is stored DUPLICATED in smem
// ((v,v) 8-byte pairs) so the broadcast operand comes straight from LDS —
// no per-iteration packing MOVs.
// ---------------------------------------------------------------------------
__global__ __launch_bounds__(256) void conv_kernel(
    const float* __restrict__ x,
    const float* __restrict__ bias)
{
    extern __shared__ float smem_dyn[];
    // x_dup: [CICHUNK][3][XCOLS] of (v,v) u64 pairs  = 25344 B
    unsigned long long (*x_dup)[3][XCOLS] =
        (unsigned long long (*)[3][XCOLS])smem_dyn;
    // w_s: [CICHUNK][9][C_OUT] floats = 36864 B
    float (*w_s)[9][C_OUT] =
        (float (*)[9][C_OUT])(smem_dyn + CICHUNK * 3 * XCOLS * 2);

    const int ho = blockIdx.y;    // 0..127
    const int b  = blockIdx.z;    // 0..7
    const int t  = threadIdx.x;
    const int lane = t & 31;
    const int warp = t >> 5;
    const int co4  = lane * 4;
    const int wo_l = warp * 8;                 // 8 wo per warp-thread
    const int wb   = blockIdx.x * WOB;

    unsigned long long acc[8][2];
    const unsigned long long z2 = bcast2(0.0f);
    #pragma unroll
    for (int i = 0; i < 8; i++) { acc[i][0] = z2; acc[i][1] = z2; }

    for (int cc = 0; cc < C_IN; cc += CICHUNK) {
        // --- cooperative load of input tile: [CICHUNK][3 rows][129 cols], duplicated
        for (int idx = t; idx < CICHUNK * 3 * XCOLS; idx += 256) {
            int c  = idx % XCOLS;
            int r  = (idx / XCOLS) % 3;
            int ci = idx / (3 * XCOLS);
            int ih = 2 * ho - 1 + r;
            int iw = 2 * wb - 1 + c;
            float v = 0.0f;
            if (c < 129 && ih >= 0 && ih < H_IN && iw >= 0 && iw < W_IN)
                v = x[(((size_t)(b * C_IN + cc + ci)) * H_IN + ih) * W_IN + iw];
            x_dup[ci][r][c] = bcast2(v);
        }
        // --- cooperative load of weight chunk (vectorized, contiguous in g_wT)
        {
            const float4* src = (const float4*)&g_wT[(size_t)cc * 9 * C_OUT];
            float4* dst = (float4*)&w_s[0][0][0];
            for (int idx = t; idx < CICHUNK * 9 * C_OUT / 4; idx += 256)
                dst[idx] = src[idx];
        }
        __syncthreads();

        #pragma unroll
        for (int ci = 0; ci < CICHUNK; ci++) {
            #pragma unroll
            for (int kh = 0; kh < 3; kh++) {
                // x dup-pairs for this warp: cols [2*wo_l, 2*wo_l+17]
                // warp-uniform address -> broadcast LDS.128, conflict-free
                const unsigned long long* xrow = &x_dup[ci][kh][2 * wo_l];
                ulonglong2 xp[9];
                #pragma unroll
                for (int q = 0; q < 9; q++)
                    xp[q] = *(const ulonglong2*)(xrow + 2 * q);
                // weight co-pairs for the 3 kw taps (8B halves of the float4)
                ulonglong2 w0 = *(const ulonglong2*)&w_s[ci][kh * 3 + 0][co4];
                ulonglong2 w1 = *(const ulonglong2*)&w_s[ci][kh * 3 + 1][co4];
                ulonglong2 w2 = *(const ulonglong2*)&w_s[ci][kh * 3 + 2][co4];
                #pragma unroll
                for (int i = 0; i < 8; i++) {
                    // taps at dup indices 2i, 2i+1, 2i+2
                    unsigned long long p0 = (2 * i    ) & 1 ? xp[(2 * i    ) >> 1].y : xp[(2 * i    ) >> 1].x;
                    unsigned long long p1 = (2 * i + 1) & 1 ? xp[(2 * i + 1) >> 1].y : xp[(2 * i + 1) >> 1].x;
                    unsigned long long p2 = (2 * i + 2) & 1 ? xp[(2 * i + 2) >> 1].y : xp[(2 * i + 2) >> 1].x;
                    fma2(acc[i][0], p0, w0.x); fma2(acc[i][1], p0, w0.y);
                    fma2(acc[i][0], p1, w1.x); fma2(acc[i][1], p1, w1.y);
                    fma2(acc[i][0], p2, w2.x); fma2(acc[i][1], p2, w2.y);
                }
            }
        }
        __syncthreads();
    }

    // --- epilogue: bias + ReLU, store NHWC-flat (float4 per wo)
    float4 bv = *(const float4*)&bias[co4];
    #pragma unroll
    for (int i = 0; i < 8; i++) {
        float a0, a1, a2, a3;
        unpack2(acc[i][0], a0, a1);
        unpack2(acc[i][1], a2, a3);
        float4 o;
        o.x = fmaxf(a0 + bv.x, 0.0f);
        o.y = fmaxf(a1 + bv.y, 0.0f);
        o.z = fmaxf(a2 + bv.z, 0.0f);
        o.w = fmaxf(a3 + bv.w, 0.0f);
        int wo = wb + wo_l + i;
        size_t pix = ((size_t)(b * H_OUT + ho)) * W_OUT + wo;
        *(float4*)&g_y[pix * C_OUT + co4] = o;
    }
}

// ---------------------------------------------------------------------------
// Kernel 2: fused gather + flattened double segment-max + additive fusion.
// One warp per 3D point. CSR-within-CSR => pixel range for point n is
// [a_ptr[v_ptr[n]], a_ptr[v_ptr[n+1]]). All values >= 0 (post-ReLU), so
// 0-initialized max == reference's isfinite->0 handling at both levels.
// Lane handles channels [lane*4, lane*4+4) as one float4.
// ---------------------------------------------------------------------------
__global__ __launch_bounds__(256) void pool_fuse_kernel(
    const float* __restrict__ x3d,
    const int*   __restrict__ fm_idx,
    const int*   __restrict__ a_ptr,
    const int*   __restrict__ v_ptr,
    float*       __restrict__ out)
{
    int warp = (blockIdx.x * blockDim.x + threadIdx.x) >> 5;
    int lane = threadIdx.x & 31;
    if (warp >= N_PTS) return;

    int v0 = v_ptr[warp];
    int v1 = v_ptr[warp + 1];
    int lo = a_ptr[v0];
    int hi = a_ptr[v1];

    float4 acc = make_float4(0.0f, 0.0f, 0.0f, 0.0f);
    int i = lo;
    // 4-wide unroll for MLP on the dependent idx->row loads
    for (; i + 4 <= hi; i += 4) {
        int r0 = fm_idx[i + 0];
        int r1 = fm_idx[i + 1];
        int r2 = fm_idx[i + 2];
        int r3 = fm_idx[i + 3];
        float4 y0 = *(const float4*)&g_y[(size_t)r0 * C_OUT + lane * 4];
        float4 y1 = *(const float4*)&g_y[(size_t)r1 * C_OUT + lane * 4];
        float4 y2 = *(const float4*)&g_y[(size_t)r2 * C_OUT + lane * 4];
        float4 y3 = *(const float4*)&g_y[(size_t)r3 * C_OUT + lane * 4];
        acc.x = fmaxf(fmaxf(fmaxf(acc.x, y0.x), fmaxf(y1.x, y2.x)), y3.x);
        acc.y = fmaxf(fmaxf(fmaxf(acc.y, y0.y), fmaxf(y1.y, y2.y)), y3.y);
        acc.z = fmaxf(fmaxf(fmaxf(acc.z, y0.z), fmaxf(y1.z, y2.z)), y3.z);
        acc.w = fmaxf(fmaxf(fmaxf(acc.w, y0.w), fmaxf(y1.w, y2.w)), y3.w);
    }
    for (; i < hi; i++) {
        int r = fm_idx[i];
        float4 yv = *(const float4*)&g_y[(size_t)r * C_OUT + lane * 4];
        acc.x = fmaxf(acc.x, yv.x);
        acc.y = fmaxf(acc.y, yv.y);
        acc.z = fmaxf(acc.z, yv.z);
        acc.w = fmaxf(acc.w, yv.w);
    }

    float4 xv = *(const float4*)&x3d[(size_t)warp * C_OUT + lane * 4];
    float4 o = make_float4(acc.x + xv.x, acc.y + xv.y, acc.z + xv.z, acc.w + xv.w);
    *(float4*)&out[(size_t)warp * C_OUT + lane * 4] = o;
}

// ---------------------------------------------------------------------------
// Launch
// Input order (metadata): x, w, b, x_3d, fm_idx, a_ptr, v_ptr
// ---------------------------------------------------------------------------
extern "C" void kernel_launch(void* const* d_in, const int* in_sizes, int n_in,
                              void* d_out, int out_size)
{
    const float* x      = (const float*)d_in[0];
    const float* w      = (const float*)d_in[1];
    const float* bias   = (const float*)d_in[2];
    const float* x3d    = (const float*)d_in[3];
    const int*   fm_idx = (const int*)d_in[4];
    const int*   a_ptr  = (const int*)d_in[5];
    const int*   v_ptr  = (const int*)d_in[6];
    float* out = (float*)d_out;

    // K0: weight transpose (73728 elems)
    wt_transpose_kernel<<<(C_IN * 9 * C_OUT + 255) / 256, 256>>>(w);

    // K1: conv + bias + relu -> g_y (NHWC-flat). ~61 KB smem -> dynamic.
    const int smem_bytes = CICHUNK * 3 * XCOLS * 8 + CICHUNK * 9 * C_OUT * 4;
    cudaFuncSetAttribute(conv_kernel, cudaFuncAttributeMaxDynamicSharedMemorySize, smem_bytes);
    dim3 cgrid(W_OUT / WOB, H_OUT, B_);
    conv_kernel<<<cgrid, 256, smem_bytes>>>(x, bias);

    // K2: fused gather + double segment-max + add
    int nblocks = (N_PTS + 7) / 8;   // 8 warps per 256-thread block
    pool_fuse_kernel<<<nblocks, 256>>>(x3d, fm_idx, a_ptr, v_ptr, out);
}

// round 6
// speedup vs baseline: 1.8932x; 1.8932x over previous
#include <cuda_runtime.h>
#include <cuda_bf16.h>

// Problem constants
#define B_    8
#define C_IN  64
#define C_OUT 128
#define H_IN  256
#define W_IN  256
#define H_OUT 128
#define W_OUT 128
#define N_PTS 50000

#define WOB    64        // output-pixel tile per block (GEMM M)
#define XS_IW  130       // input cols covered: 2*WOB + 2
#define XS_PAD 36        // ci-chunk(32) padded to 36 words: frag reads = 2-phase min
#define WS_PAD 40        // ci-chunk(32) padded to 40 words: frag reads = 2-phase min

// Scratch: conv output NHWC-flat [B*H_OUT*W_OUT, C_OUT] (67 MB)
__device__ __align__(256) float g_y[(size_t)B_ * H_OUT * W_OUT * C_OUT];
// Weights as tf32 bits, [tap][co][ci]
__device__ __align__(256) unsigned g_wT2[9 * C_OUT * C_IN];

__device__ __forceinline__ unsigned f2tf32(float v) {
    unsigned r; asm("cvt.rna.tf32.f32 %0, %1;" : "=r"(r) : "f"(v)); return r;
}

// ---------------------------------------------------------------------------
// Kernel 0: weights (C_OUT,C_IN,3,3) -> tf32 [tap][co][ci]
// ---------------------------------------------------------------------------
__global__ void wt_kernel(const float* __restrict__ w) {
    int idx = blockIdx.x * blockDim.x + threadIdx.x;
    if (idx >= 9 * C_OUT * C_IN) return;
    int ci  = idx % C_IN;
    int co  = (idx / C_IN) % C_OUT;
    int tap = idx / (C_IN * C_OUT);
    g_wT2[idx] = f2tf32(w[(co * C_IN + ci) * 9 + tap]);
}

// ---------------------------------------------------------------------------
// Kernel 1: implicit-GEMM conv via mma.sync tf32.
// Block: 256 thr (8 warps), tile M=64 pixels x N=128 co, K=576 (2 ci-chunks x 9 taps x 4 k8).
// Warp (wm 0..1, wn 0..3): 32 rows x 32 cols = 2 m16 x 4 n8 frags.
// ---------------------------------------------------------------------------
__global__ __launch_bounds__(256, 2) void conv_kernel(
    const float* __restrict__ x,
    const float* __restrict__ bias)
{
    extern __shared__ unsigned smem[];
    unsigned* xs = smem;                       // [3][XS_IW][XS_PAD] tf32 bits
    unsigned* ws = smem + 3 * XS_IW * XS_PAD;  // [C_OUT][WS_PAD]    tf32 bits

    const int ho = blockIdx.y;
    const int b  = blockIdx.z;
    const int wb = blockIdx.x * WOB;
    const int t  = threadIdx.x;
    const int lane = t & 31, warp = t >> 5;
    const int wm = warp >> 2;        // 0..1
    const int wn = warp & 3;         // 0..3
    const int lq = lane >> 2;        // 0..7
    const int lr = lane & 3;         // 0..3

    float acc[2][4][4] = {};

    for (int cc = 0; cc < C_IN; cc += 32) {
        __syncthreads();   // xs free (prev chunk's MMAs done)
        // ---- fill xs: 3 rows x 130 iw x 32 ci (tf32), STS.128 per thread
        for (int it = warp; it < 120; it += 8) {
            int iwb = it % 5, r = (it / 5) % 3, ci4 = it / 15;
            int iw  = iwb * 32 + lane;
            int ih  = 2 * ho - 1 + r;
            int iwg = 2 * wb - 1 + iw;
            unsigned u0 = 0, u1 = 0, u2 = 0, u3 = 0;
            if (iw < XS_IW && ih >= 0 && ih < H_IN && iwg >= 0 && iwg < W_IN) {
                const float* p = &x[(((size_t)(b * C_IN + cc + ci4 * 4)) * H_IN + ih) * W_IN + iwg];
                u0 = f2tf32(p[0]);
                u1 = f2tf32(p[(size_t)H_IN * W_IN]);
                u2 = f2tf32(p[(size_t)2 * H_IN * W_IN]);
                u3 = f2tf32(p[(size_t)3 * H_IN * W_IN]);
            }
            if (iw < XS_IW)
                *(uint4*)&xs[(r * XS_IW + iw) * XS_PAD + ci4 * 4] = make_uint4(u0, u1, u2, u3);
        }

        for (int tap = 0; tap < 9; tap++) {
            const int kh = tap / 3, kw = tap % 3;
            __syncthreads();   // ws free / xs ready
            // ---- fill ws: [128 co][32 ci] for this tap+chunk
            #pragma unroll
            for (int j = 0; j < 4; j++) {
                int idx4 = t + 256 * j;         // 0..1023
                int ci4 = idx4 & 7, co = idx4 >> 3;
                uint4 v = *(const uint4*)&g_wT2[(tap * C_OUT + co) * C_IN + cc + ci4 * 4];
                *(uint4*)&ws[co * WS_PAD + ci4 * 4] = v;
            }
            __syncthreads();   // ws ready

            #pragma unroll
            for (int k8 = 0; k8 < 4; k8++) {
                uint2 bf[4];
                #pragma unroll
                for (int j8 = 0; j8 < 4; j8++)
                    bf[j8] = *(const uint2*)&ws[(wn * 32 + j8 * 8 + lq) * WS_PAD + k8 * 8 + 2 * lr];
                #pragma unroll
                for (int i16 = 0; i16 < 2; i16++) {
                    int m0  = wm * 32 + i16 * 16 + lq;
                    int iw0 = 2 * m0 + kw;
                    uint2 a02 = *(const uint2*)&xs[(kh * XS_IW + iw0) * XS_PAD + k8 * 8 + 2 * lr];
                    uint2 a13 = *(const uint2*)&xs[(kh * XS_IW + iw0 + 16) * XS_PAD + k8 * 8 + 2 * lr];
                    #pragma unroll
                    for (int j8 = 0; j8 < 4; j8++) {
                        asm volatile(
                            "mma.sync.aligned.m16n8k8.row.col.f32.tf32.tf32.f32 "
                            "{%0,%1,%2,%3}, {%4,%5,%6,%7}, {%8,%9}, {%0,%1,%2,%3};"
                            : "+f"(acc[i16][j8][0]), "+f"(acc[i16][j8][1]),
                              "+f"(acc[i16][j8][2]), "+f"(acc[i16][j8][3])
                            : "r"(a02.x), "r"(a13.x), "r"(a02.y), "r"(a13.y),
                              "r"(bf[j8].x), "r"(bf[j8].y));
                    }
                }
            }
        }
    }

    // ---- epilogue: bias + ReLU -> g_y NHWC-flat
    size_t pixbase = ((size_t)(b * H_OUT + ho)) * W_OUT + wb;
    #pragma unroll
    for (int i16 = 0; i16 < 2; i16++) {
        int m0 = wm * 32 + i16 * 16 + lq;
        #pragma unroll
        for (int j8 = 0; j8 < 4; j8++) {
            int co = wn * 32 + j8 * 8 + 2 * lr;
            float b0 = bias[co], b1 = bias[co + 1];
            float2 lo = make_float2(fmaxf(acc[i16][j8][0] + b0, 0.f),
                                    fmaxf(acc[i16][j8][1] + b1, 0.f));
            float2 hi = make_float2(fmaxf(acc[i16][j8][2] + b0, 0.f),
                                    fmaxf(acc[i16][j8][3] + b1, 0.f));
            *(float2*)&g_y[(pixbase + m0) * C_OUT + co]     = lo;
            *(float2*)&g_y[(pixbase + m0 + 8) * C_OUT + co] = hi;
        }
    }
}

// ---------------------------------------------------------------------------
// Kernel 2: fused gather + flattened double segment-max + additive fusion.
// One warp per 3D point; range = [a_ptr[v_ptr[n]], a_ptr[v_ptr[n+1]]).
// Post-ReLU values >= 0 => 0-init max == reference empty-segment semantics.
// ---------------------------------------------------------------------------
__global__ __launch_bounds__(256) void pool_fuse_kernel(
    const float* __restrict__ x3d,
    const int*   __restrict__ fm_idx,
    const int*   __restrict__ a_ptr,
    const int*   __restrict__ v_ptr,
    float*       __restrict__ out)
{
    int warp = (blockIdx.x * blockDim.x + threadIdx.x) >> 5;
    int lane = threadIdx.x & 31;
    if (warp >= N_PTS) return;

    int lo = a_ptr[v_ptr[warp]];
    int hi = a_ptr[v_ptr[warp + 1]];

    float4 acc = make_float4(0.0f, 0.0f, 0.0f, 0.0f);
    int i = lo;
    for (; i + 4 <= hi; i += 4) {
        int r0 = fm_idx[i + 0];
        int r1 = fm_idx[i + 1];
        int r2 = fm_idx[i + 2];
        int r3 = fm_idx[i + 3];
        float4 y0 = *(const float4*)&g_y[(size_t)r0 * C_OUT + lane * 4];
        float4 y1 = *(const float4*)&g_y[(size_t)r1 * C_OUT + lane * 4];
        float4 y2 = *(const float4*)&g_y[(size_t)r2 * C_OUT + lane * 4];
        float4 y3 = *(const float4*)&g_y[(size_t)r3 * C_OUT + lane * 4];
        acc.x = fmaxf(fmaxf(fmaxf(acc.x, y0.x), fmaxf(y1.x, y2.x)), y3.x);
        acc.y = fmaxf(fmaxf(fmaxf(acc.y, y0.y), fmaxf(y1.y, y2.y)), y3.y);
        acc.z = fmaxf(fmaxf(fmaxf(acc.z, y0.z), fmaxf(y1.z, y2.z)), y3.z);
        acc.w = fmaxf(fmaxf(fmaxf(acc.w, y0.w), fmaxf(y1.w, y2.w)), y3.w);
    }
    for (; i < hi; i++) {
        int r = fm_idx[i];
        float4 yv = *(const float4*)&g_y[(size_t)r * C_OUT + lane * 4];
        acc.x = fmaxf(acc.x, yv.x);
        acc.y = fmaxf(acc.y, yv.y);
        acc.z = fmaxf(acc.z, yv.z);
        acc.w = fmaxf(acc.w, yv.w);
    }

    float4 xv = *(const float4*)&x3d[(size_t)warp * C_OUT + lane * 4];
    *(float4*)&out[(size_t)warp * C_OUT + lane * 4] =
        make_float4(acc.x + xv.x, acc.y + xv.y, acc.z + xv.z, acc.w + xv.w);
}

// ---------------------------------------------------------------------------
// Launch: inputs x, w, b, x_3d, fm_idx, a_ptr, v_ptr
// ---------------------------------------------------------------------------
extern "C" void kernel_launch(void* const* d_in, const int* in_sizes, int n_in,
                              void* d_out, int out_size)
{
    const float* x      = (const float*)d_in[0];
    const float* w      = (const float*)d_in[1];
    const float* bias   = (const float*)d_in[2];
    const float* x3d    = (const float*)d_in[3];
    const int*   fm_idx = (const int*)d_in[4];
    const int*   a_ptr  = (const int*)d_in[5];
    const int*   v_ptr  = (const int*)d_in[6];
    float* out = (float*)d_out;

    wt_kernel<<<(9 * C_OUT * C_IN + 255) / 256, 256>>>(w);

    const int smem_bytes = (3 * XS_IW * XS_PAD + C_OUT * WS_PAD) * (int)sizeof(unsigned);
    cudaFuncSetAttribute(conv_kernel, cudaFuncAttributeMaxDynamicSharedMemorySize, smem_bytes);
    dim3 cgrid(W_OUT / WOB, H_OUT, B_);
    conv_kernel<<<cgrid, 256, smem_bytes>>>(x, bias);

    int nblocks = (N_PTS + 7) / 8;
    pool_fuse_kernel<<<nblocks, 256>>>(x3d, fm_idx, a_ptr, v_ptr, out);
}

// round 7
// speedup vs baseline: 2.1099x; 1.1145x over previous
#include <cuda_runtime.h>
#include <cuda_bf16.h>

// Problem constants
#define B_    8
#define C_IN  64
#define C_OUT 128
#define H_IN  256
#define W_IN  256
#define H_OUT 128
#define W_OUT 128
#define N_PTS 50000

#define MTILE   128      // one full ho row (wo 0..127) per block
#define CICHUNK 16       // ci per chunk (4 chunks)
#define XS_IW   258      // input cols: 2*128 + 2
#define XS_PAD  20       // (2*20*lq*4+8lr)/8 = (20lq+lr) mod 32 injective -> conflict-free
#define WS_PAD  24       // (24*lq*4+8lr)/8 = (12lq+lr) mod 32 injective -> conflict-free
#define XS_WORDS (3 * XS_IW * XS_PAD)          // 15480
#define WS_WORDS (C_OUT * WS_PAD)              // 3072 per buffer

// Scratch: conv output NHWC-flat [B*H_OUT*W_OUT, C_OUT] (67 MB)
__device__ __align__(256) float g_y[(size_t)B_ * H_OUT * W_OUT * C_OUT];
// Weights as tf32 bits, [tap][co][ci]
__device__ __align__(256) unsigned g_wT2[9 * C_OUT * C_IN];

__device__ __forceinline__ unsigned f2tf32(float v) {
    unsigned r; asm("cvt.rna.tf32.f32 %0, %1;" : "=r"(r) : "f"(v)); return r;
}

// ---------------------------------------------------------------------------
// Kernel 0: weights (C_OUT,C_IN,3,3) -> tf32 [tap][co][ci]
// ---------------------------------------------------------------------------
__global__ void wt_kernel(const float* __restrict__ w) {
    int idx = blockIdx.x * blockDim.x + threadIdx.x;
    if (idx >= 9 * C_OUT * C_IN) return;
    int ci  = idx % C_IN;
    int co  = (idx / C_IN) % C_OUT;
    int tap = idx / (C_IN * C_OUT);
    g_wT2[idx] = f2tf32(w[(co * C_IN + ci) * 9 + tap]);
}

// ---------------------------------------------------------------------------
// Kernel 1: implicit-GEMM conv via mma.sync tf32.
// Block: 256 thr (8 warps), tile M=128 pixels (one ho row) x N=128 co.
// Warp (wm 0..3, wn 0..1): 32 rows x 64 cols = 2 m16 x 8 n8 frags.
// K loop: 4 ci-chunks x 9 taps x 2 k8. ws double-buffered with register
// prefetch of the next tap during the current tap's MMAs -> 1 sync per tap.
// ---------------------------------------------------------------------------
__global__ __launch_bounds__(256, 2) void conv_kernel(
    const float* __restrict__ x,
    const float* __restrict__ bias)
{
    extern __shared__ unsigned smem[];
    unsigned* xs  = smem;                    // [3][XS_IW][XS_PAD]
    unsigned* ws0 = smem + XS_WORDS;         // [C_OUT][WS_PAD] buffer 0
    unsigned* ws1 = ws0 + WS_WORDS;          // buffer 1

    const int ho = blockIdx.x;
    const int b  = blockIdx.y;
    const int t  = threadIdx.x;
    const int lane = t & 31, warp = t >> 5;
    const int wm = warp >> 1;        // 0..3  (32 m-rows each)
    const int wn = warp & 1;         // 0..1  (64 co each)
    const int lq = lane >> 2;        // 0..7
    const int lr = lane & 3;         // 0..3

    // weight prefetch mapping: thread covers idx4 = t, t+256
    const int pf_ci4_0 = t & 3,        pf_co_0 = t >> 2;
    const int pf_ci4_1 = (t + 256) & 3, pf_co_1 = (t + 256) >> 2;

    float acc[2][8][4] = {};

    // prefetch (chunk 0, tap 0)
    uint4 pre0 = *(const uint4*)&g_wT2[(0 * C_OUT + pf_co_0) * C_IN + 0 + pf_ci4_0 * 4];
    uint4 pre1 = *(const uint4*)&g_wT2[(0 * C_OUT + pf_co_1) * C_IN + 0 + pf_ci4_1 * 4];

    for (int cc = 0; cc < C_IN; cc += CICHUNK) {
        __syncthreads();   // xs free (prev chunk MMAs done)
        // ---- fill xs: 3 rows x 258 iw x 16 ci (tf32), STS.128 along ci
        for (int i = t; i < 3 * XS_IW * 4; i += 256) {
            int ci4 = i / (3 * XS_IW);
            int rem = i % (3 * XS_IW);
            int r   = rem / XS_IW;
            int iw  = rem % XS_IW;
            int ih  = 2 * ho - 1 + r;
            int iwg = iw - 1;
            unsigned u0 = 0, u1 = 0, u2 = 0, u3 = 0;
            if (ih >= 0 && ih < H_IN && iwg >= 0 && iwg < W_IN) {
                const float* p = &x[(((size_t)(b * C_IN + cc + ci4 * 4)) * H_IN + ih) * W_IN + iwg];
                u0 = f2tf32(p[0]);
                u1 = f2tf32(p[(size_t)H_IN * W_IN]);
                u2 = f2tf32(p[(size_t)2 * H_IN * W_IN]);
                u3 = f2tf32(p[(size_t)3 * H_IN * W_IN]);
            }
            *(uint4*)&xs[(r * XS_IW + iw) * XS_PAD + ci4 * 4] = make_uint4(u0, u1, u2, u3);
        }
        __syncthreads();   // xs ready

        for (int tap = 0; tap < 9; tap++) {
            const int kh = tap / 3, kw = tap % 3;
            unsigned* ws = (tap & 1) ? ws1 : ws0;
            // store prefetched weights for this tap
            *(uint4*)&ws[pf_co_0 * WS_PAD + pf_ci4_0 * 4] = pre0;
            *(uint4*)&ws[pf_co_1 * WS_PAD + pf_ci4_1 * 4] = pre1;
            // prefetch next (tap, chunk) pair
            {
                int ntap = tap + 1, ncc = cc;
                if (ntap == 9) { ntap = 0; ncc = cc + CICHUNK; }
                if (ncc < C_IN) {
                    pre0 = *(const uint4*)&g_wT2[(ntap * C_OUT + pf_co_0) * C_IN + ncc + pf_ci4_0 * 4];
                    pre1 = *(const uint4*)&g_wT2[(ntap * C_OUT + pf_co_1) * C_IN + ncc + pf_ci4_1 * 4];
                }
            }
            __syncthreads();   // ws ready (and prev tap's MMAs done block-wide)

            #pragma unroll
            for (int k8 = 0; k8 < 2; k8++) {
                uint2 bf[8];
                #pragma unroll
                for (int j8 = 0; j8 < 8; j8++)
                    bf[j8] = *(const uint2*)&ws[(wn * 64 + j8 * 8 + lq) * WS_PAD + k8 * 8 + 2 * lr];
                #pragma unroll
                for (int i16 = 0; i16 < 2; i16++) {
                    int m0  = wm * 32 + i16 * 16 + lq;
                    int iw0 = 2 * m0 + kw;
                    uint2 a02 = *(const uint2*)&xs[(kh * XS_IW + iw0) * XS_PAD + k8 * 8 + 2 * lr];
                    uint2 a13 = *(const uint2*)&xs[(kh * XS_IW + iw0 + 16) * XS_PAD + k8 * 8 + 2 * lr];
                    #pragma unroll
                    for (int j8 = 0; j8 < 8; j8++) {
                        asm volatile(
                            "mma.sync.aligned.m16n8k8.row.col.f32.tf32.tf32.f32 "
                            "{%0,%1,%2,%3}, {%4,%5,%6,%7}, {%8,%9}, {%0,%1,%2,%3};"
                            : "+f"(acc[i16][j8][0]), "+f"(acc[i16][j8][1]),
                              "+f"(acc[i16][j8][2]), "+f"(acc[i16][j8][3])
                            : "r"(a02.x), "r"(a13.x), "r"(a02.y), "r"(a13.y),
                              "r"(bf[j8].x), "r"(bf[j8].y));
                    }
                }
            }
        }
    }

    // ---- epilogue: bias + ReLU -> g_y NHWC-flat
    size_t pixbase = ((size_t)(b * H_OUT + ho)) * W_OUT;
    #pragma unroll
    for (int i16 = 0; i16 < 2; i16++) {
        int m0 = wm * 32 + i16 * 16 + lq;
        #pragma unroll
        for (int j8 = 0; j8 < 8; j8++) {
            int co = wn * 64 + j8 * 8 + 2 * lr;
            float b0 = bias[co], b1 = bias[co + 1];
            float2 lo = make_float2(fmaxf(acc[i16][j8][0] + b0, 0.f),
                                    fmaxf(acc[i16][j8][1] + b1, 0.f));
            float2 hi = make_float2(fmaxf(acc[i16][j8][2] + b0, 0.f),
                                    fmaxf(acc[i16][j8][3] + b1, 0.f));
            *(float2*)&g_y[(pixbase + m0) * C_OUT + co]     = lo;
            *(float2*)&g_y[(pixbase + m0 + 8) * C_OUT + co] = hi;
        }
    }
}

// ---------------------------------------------------------------------------
// Kernel 2: fused gather + flattened double segment-max + additive fusion.
// One warp per 3D point; range = [a_ptr[v_ptr[n]], a_ptr[v_ptr[n+1]]).
// Post-ReLU values >= 0 => 0-init max == reference empty-segment semantics.
// ---------------------------------------------------------------------------
__global__ __launch_bounds__(256) void pool_fuse_kernel(
    const float* __restrict__ x3d,
    const int*   __restrict__ fm_idx,
    const int*   __restrict__ a_ptr,
    const int*   __restrict__ v_ptr,
    float*       __restrict__ out)
{
    int warp = (blockIdx.x * blockDim.x + threadIdx.x) >> 5;
    int lane = threadIdx.x & 31;
    if (warp >= N_PTS) return;

    int lo = a_ptr[v_ptr[warp]];
    int hi = a_ptr[v_ptr[warp + 1]];

    float4 acc = make_float4(0.0f, 0.0f, 0.0f, 0.0f);
    int i = lo;
    for (; i + 4 <= hi; i += 4) {
        int r0 = fm_idx[i + 0];
        int r1 = fm_idx[i + 1];
        int r2 = fm_idx[i + 2];
        int r3 = fm_idx[i + 3];
        float4 y0 = *(const float4*)&g_y[(size_t)r0 * C_OUT + lane * 4];
        float4 y1 = *(const float4*)&g_y[(size_t)r1 * C_OUT + lane * 4];
        float4 y2 = *(const float4*)&g_y[(size_t)r2 * C_OUT + lane * 4];
        float4 y3 = *(const float4*)&g_y[(size_t)r3 * C_OUT + lane * 4];
        acc.x = fmaxf(fmaxf(fmaxf(acc.x, y0.x), fmaxf(y1.x, y2.x)), y3.x);
        acc.y = fmaxf(fmaxf(fmaxf(acc.y, y0.y), fmaxf(y1.y, y2.y)), y3.y);
        acc.z = fmaxf(fmaxf(fmaxf(acc.z, y0.z), fmaxf(y1.z, y2.z)), y3.z);
        acc.w = fmaxf(fmaxf(fmaxf(acc.w, y0.w), fmaxf(y1.w, y2.w)), y3.w);
    }
    for (; i < hi; i++) {
        int r = fm_idx[i];
        float4 yv = *(const float4*)&g_y[(size_t)r * C_OUT + lane * 4];
        acc.x = fmaxf(acc.x, yv.x);
        acc.y = fmaxf(acc.y, yv.y);
        acc.z = fmaxf(acc.z, yv.z);
        acc.w = fmaxf(acc.w, yv.w);
    }

    float4 xv = *(const float4*)&x3d[(size_t)warp * C_OUT + lane * 4];
    *(float4*)&out[(size_t)warp * C_OUT + lane * 4] =
        make_float4(acc.x + xv.x, acc.y + xv.y, acc.z + xv.z, acc.w + xv.w);
}

// ---------------------------------------------------------------------------
// Launch: inputs x, w, b, x_3d, fm_idx, a_ptr, v_ptr
// ---------------------------------------------------------------------------
extern "C" void kernel_launch(void* const* d_in, const int* in_sizes, int n_in,
                              void* d_out, int out_size)
{
    const float* x      = (const float*)d_in[0];
    const float* w      = (const float*)d_in[1];
    const float* bias   = (const float*)d_in[2];
    const float* x3d    = (const float*)d_in[3];
    const int*   fm_idx = (const int*)d_in[4];
    const int*   a_ptr  = (const int*)d_in[5];
    const int*   v_ptr  = (const int*)d_in[6];
    float* out = (float*)d_out;

    wt_kernel<<<(9 * C_OUT * C_IN + 255) / 256, 256>>>(w);

    const int smem_bytes = (XS_WORDS + 2 * WS_WORDS) * (int)sizeof(unsigned);
    cudaFuncSetAttribute(conv_kernel, cudaFuncAttributeMaxDynamicSharedMemorySize, smem_bytes);
    dim3 cgrid(H_OUT, B_);
    conv_kernel<<<cgrid, 256, smem_bytes>>>(x, bias);

    int nblocks = (N_PTS + 7) / 8;
    pool_fuse_kernel<<<nblocks, 256>>>(x3d, fm_idx, a_ptr, v_ptr, out);
}

// round 9
// speedup vs baseline: 3.0203x; 1.4315x over previous
#include <cuda_runtime.h>
#include <cuda_fp16.h>
#include <cstdint>

// Problem constants
#define B_    8
#define C_IN  64
#define C_OUT 128
#define H_IN  256
#define W_IN  256
#define H_OUT 128
#define W_OUT 128
#define N_PTS 50000

#define CICHUNK 16       // ci per chunk (4 chunks); one k16 MMA per tap-chunk
#define XS_IW   258      // input cols: 2*128 + 2
#define ROWP    12       // words per row (8 fp16x2 words + 4 pad): 12*lq+lr mod 32 injective
#define XS_WORDS (3 * XS_IW * ROWP)     // 9288
#define WS_WORDS (C_OUT * ROWP)         // 1536 per buffer

// Scratch: conv output NHWC-flat [B*H_OUT*W_OUT, C_OUT] (67 MB)
__device__ __align__(256) float g_y[(size_t)B_ * H_OUT * W_OUT * C_OUT];
// Weights as fp16x2 words, [tap][co][8 words] (ci pairs in natural order)
__device__ __align__(256) unsigned g_wH[9 * C_OUT * (C_IN / 2)];

// ---------------------------------------------------------------------------
// Kernel 0: weights (C_OUT,C_IN,3,3) -> fp16x2 [tap][co][ci/2]
// ---------------------------------------------------------------------------
__global__ void wt_kernel(const float* __restrict__ w) {
    int idx = blockIdx.x * blockDim.x + threadIdx.x;     // over 9*128*32 pairs
    if (idx >= 9 * C_OUT * (C_IN / 2)) return;
    int pr  = idx % (C_IN / 2);
    int co  = (idx / (C_IN / 2)) % C_OUT;
    int tap = idx / ((C_IN / 2) * C_OUT);
    float w0 = w[(co * C_IN + 2 * pr) * 9 + tap];
    float w1 = w[(co * C_IN + 2 * pr + 1) * 9 + tap];
    __half2 h = __floats2half2_rn(w0, w1);               // low = even ci
    g_wH[idx] = *(unsigned*)&h;
}

// ---------------------------------------------------------------------------
// Kernel 1: implicit-GEMM conv via mma.sync m16n8k16 fp16 (fp32 accum).
// Block: 256 thr (8 warps), tile M=128 pixels (one ho row) x N=128 co.
// Warp (wm 0..3, wn 0..1): 32 rows x 64 cols = 2 m16 x 8 n8 frags.
// K loop: 4 ci-chunks x 9 taps, one k16 MMA step each. ws double-buffered
// with register prefetch of the next tap during current tap's MMAs.
// ---------------------------------------------------------------------------
__global__ __launch_bounds__(256, 2) void conv_kernel(
    const float* __restrict__ x,
    const float* __restrict__ bias)
{
    extern __shared__ unsigned smem[];
    unsigned* xs  = smem;                    // [3][XS_IW][ROWP] fp16x2 words
    unsigned* ws0 = smem + XS_WORDS;         // [C_OUT][ROWP] buffer 0
    unsigned* ws1 = ws0 + WS_WORDS;          // buffer 1

    const int ho = blockIdx.x;
    const int b  = blockIdx.y;
    const int t  = threadIdx.x;
    const int lane = t & 31, warp = t >> 5;
    const int wm = warp >> 1;        // 0..3  (32 m-rows each)
    const int wn = warp & 1;         // 0..1  (64 co each)
    const int lq = lane >> 2;        // 0..7  (groupID)
    const int lr = lane & 3;         // 0..3  (threadID in group)

    // weight prefetch mapping: thread covers co = t>>1, uint4 at half = t&1
    const int pf_co = t >> 1, pf_half = t & 1;

    float acc[2][8][4] = {};

    // prefetch (chunk 0, tap 0): 16B of co's fp16 row
    uint4 pre = *(const uint4*)&g_wH[(0 * C_OUT + pf_co) * (C_IN / 2) + 0 + pf_half * 4];

    for (int cc = 0; cc < C_IN; cc += CICHUNK) {
        __syncthreads();   // xs free (prev chunk MMAs done)
        // ---- fill xs: [3 kh][258 iw] x 16 ci as 8 fp16x2 words, pitch ROWP
        for (int i = t; i < 3 * XS_IW * 2; i += 256) {
            int half = i / (3 * XS_IW);             // ci half: 0 -> ci 0..7, 1 -> 8..15
            int rem  = i % (3 * XS_IW);
            int r    = rem / XS_IW;
            int iw   = rem % XS_IW;
            int ih   = 2 * ho - 1 + r;
            int iwg  = iw - 1;
            unsigned u[4] = {0, 0, 0, 0};
            if (ih >= 0 && ih < H_IN && iwg >= 0 && iwg < W_IN) {
                const float* p = &x[(((size_t)(b * C_IN + cc + half * 8)) * H_IN + ih) * W_IN + iwg];
                #pragma unroll
                for (int j = 0; j < 4; j++) {
                    float f0 = p[(size_t)(2 * j) * H_IN * W_IN];
                    float f1 = p[(size_t)(2 * j + 1) * H_IN * W_IN];
                    __half2 h = __floats2half2_rn(f0, f1);
                    u[j] = *(unsigned*)&h;
                }
            }
            *(uint4*)&xs[(r * XS_IW + iw) * ROWP + half * 4] = make_uint4(u[0], u[1], u[2], u[3]);
        }
        __syncthreads();   // xs ready

        for (int tap = 0; tap < 9; tap++) {
            const int kh = tap / 3, kw = tap % 3;
            unsigned* ws = (tap & 1) ? ws1 : ws0;
            // store prefetched weights for this tap
            *(uint4*)&ws[pf_co * ROWP + pf_half * 4] = pre;
            // prefetch next (tap, chunk) pair
            {
                int ntap = tap + 1, ncc = cc;
                if (ntap == 9) { ntap = 0; ncc = cc + CICHUNK; }
                if (ncc < C_IN)
                    pre = *(const uint4*)&g_wH[(ntap * C_OUT + pf_co) * (C_IN / 2) + (ncc / 2) + pf_half * 4];
            }
            __syncthreads();   // ws ready (prev tap's MMAs done block-wide)

            // B fragments: col = wn*64 + j8*8 + lq; b0 = word[lr], b1 = word[lr+4]
            unsigned bf0[8], bf1[8];
            #pragma unroll
            for (int j8 = 0; j8 < 8; j8++) {
                const unsigned* br = &ws[(wn * 64 + j8 * 8 + lq) * ROWP];
                bf0[j8] = br[lr];
                bf1[j8] = br[lr + 4];
            }
            #pragma unroll
            for (int i16 = 0; i16 < 2; i16++) {
                int m0  = wm * 32 + i16 * 16 + lq;     // rows lq and lq+8 of this m16
                const unsigned* xr0 = &xs[(kh * XS_IW + 2 * m0 + kw) * ROWP];
                const unsigned* xr1 = &xs[(kh * XS_IW + 2 * (m0 + 8) + kw) * ROWP];
                unsigned a0 = xr0[lr];
                unsigned a1 = xr1[lr];
                unsigned a2 = xr0[lr + 4];
                unsigned a3 = xr1[lr + 4];
                #pragma unroll
                for (int j8 = 0; j8 < 8; j8++) {
                    asm volatile(
                        "mma.sync.aligned.m16n8k16.row.col.f32.f16.f16.f32 "
                        "{%0,%1,%2,%3}, {%4,%5,%6,%7}, {%8,%9}, {%0,%1,%2,%3};"
                        : "+f"(acc[i16][j8][0]), "+f"(acc[i16][j8][1]),
                          "+f"(acc[i16][j8][2]), "+f"(acc[i16][j8][3])
                        : "r"(a0), "r"(a1), "r"(a2), "r"(a3),
                          "r"(bf0[j8]), "r"(bf1[j8]));
                }
            }
        }
    }

    // ---- epilogue: bias + ReLU -> g_y NHWC-flat
    size_t pixbase = ((size_t)(b * H_OUT + ho)) * W_OUT;
    #pragma unroll
    for (int i16 = 0; i16 < 2; i16++) {
        int m0 = wm * 32 + i16 * 16 + lq;
        #pragma unroll
        for (int j8 = 0; j8 < 8; j8++) {
            int co = wn * 64 + j8 * 8 + 2 * lr;
            float b0 = bias[co], b1 = bias[co + 1];
            float2 lo = make_float2(fmaxf(acc[i16][j8][0] + b0, 0.f),
                                    fmaxf(acc[i16][j8][1] + b1, 0.f));
            float2 hi = make_float2(fmaxf(acc[i16][j8][2] + b0, 0.f),
                                    fmaxf(acc[i16][j8][3] + b1, 0.f));
            *(float2*)&g_y[(pixbase + m0) * C_OUT + co]     = lo;
            *(float2*)&g_y[(pixbase + m0 + 8) * C_OUT + co] = hi;
        }
    }
}

// ---------------------------------------------------------------------------
// Kernel 2: fused gather + flattened double segment-max + additive fusion.
// One warp per 3D point; range = [a_ptr[v_ptr[n]], a_ptr[v_ptr[n+1]]).
// Post-ReLU values >= 0 => 0-init max == reference empty-segment semantics.
// ---------------------------------------------------------------------------
__global__ __launch_bounds__(256) void pool_fuse_kernel(
    const float* __restrict__ x3d,
    const int*   __restrict__ fm_idx,
    const int*   __restrict__ a_ptr,
    const int*   __restrict__ v_ptr,
    float*       __restrict__ out)
{
    int warp = (blockIdx.x * blockDim.x + threadIdx.x) >> 5;
    int lane = threadIdx.x & 31;
    if (warp >= N_PTS) return;

    int lo = a_ptr[v_ptr[warp]];
    int hi = a_ptr[v_ptr[warp + 1]];

    float4 acc = make_float4(0.0f, 0.0f, 0.0f, 0.0f);
    int i = lo;
    for (; i + 4 <= hi; i += 4) {
        int r0 = fm_idx[i + 0];
        int r1 = fm_idx[i + 1];
        int r2 = fm_idx[i + 2];
        int r3 = fm_idx[i + 3];
        float4 y0 = *(const float4*)&g_y[(size_t)r0 * C_OUT + lane * 4];
        float4 y1 = *(const float4*)&g_y[(size_t)r1 * C_OUT + lane * 4];
        float4 y2 = *(const float4*)&g_y[(size_t)r2 * C_OUT + lane * 4];
        float4 y3 = *(const float4*)&g_y[(size_t)r3 * C_OUT + lane * 4];
        acc.x = fmaxf(fmaxf(fmaxf(acc.x, y0.x), fmaxf(y1.x, y2.x)), y3.x);
        acc.y = fmaxf(fmaxf(fmaxf(acc.y, y0.y), fmaxf(y1.y, y2.y)), y3.y);
        acc.z = fmaxf(fmaxf(fmaxf(acc.z, y0.z), fmaxf(y1.z, y2.z)), y3.z);
        acc.w = fmaxf(fmaxf(fmaxf(acc.w, y0.w), fmaxf(y1.w, y2.w)), y3.w);
    }
    for (; i < hi; i++) {
        int r = fm_idx[i];
        float4 yv = *(const float4*)&g_y[(size_t)r * C_OUT + lane * 4];
        acc.x = fmaxf(acc.x, yv.x);
        acc.y = fmaxf(acc.y, yv.y);
        acc.z = fmaxf(acc.z, yv.z);
        acc.w = fmaxf(acc.w, yv.w);
    }

    float4 xv = *(const float4*)&x3d[(size_t)warp * C_OUT + lane * 4];
    *(float4*)&out[(size_t)warp * C_OUT + lane * 4] =
        make_float4(acc.x + xv.x, acc.y + xv.y, acc.z + xv.z, acc.w + xv.w);
}

// ---------------------------------------------------------------------------
// Launch: inputs x, w, b, x_3d, fm_idx, a_ptr, v_ptr
// ---------------------------------------------------------------------------
extern "C" void kernel_launch(void* const* d_in, const int* in_sizes, int n_in,
                              void* d_out, int out_size)
{
    const float* x      = (const float*)d_in[0];
    const float* w      = (const float*)d_in[1];
    const float* bias   = (const float*)d_in[2];
    const float* x3d    = (const float*)d_in[3];
    const int*   fm_idx = (const int*)d_in[4];
    const int*   a_ptr  = (const int*)d_in[5];
    const int*   v_ptr  = (const int*)d_in[6];
    float* out = (float*)d_out;

    wt_kernel<<<(9 * C_OUT * (C_IN / 2) + 255) / 256, 256>>>(w);

    const int smem_bytes = (XS_WORDS + 2 * WS_WORDS) * (int)sizeof(unsigned);
    cudaFuncSetAttribute(conv_kernel, cudaFuncAttributeMaxDynamicSharedMemorySize, smem_bytes);
    dim3 cgrid(H_OUT, B_);
    conv_kernel<<<cgrid, 256, smem_bytes>>>(x, bias);

    int nblocks = (N_PTS + 7) / 8;
    pool_fuse_kernel<<<nblocks, 256>>>(x3d, fm_idx, a_ptr, v_ptr, out);
}

// round 10
// speedup vs baseline: 3.1036x; 1.0276x over previous
#include <cuda_runtime.h>
#include <cuda_fp16.h>
#include <cstdint>

// Problem constants
#define B_    8
#define C_IN  64
#define C_OUT 128
#define H_IN  256
#define W_IN  256
#define H_OUT 128
#define W_OUT 128
#define N_PTS 50000

#define CICHUNK 16       // ci per chunk (4 chunks); one k16 MMA per tap-chunk
#define XS_IW   258      // input cols: 2*128 + 2
#define ROWP    12       // words per row (8 fp16x2 + 4 pad): 12*lq+lr mod 32 injective
#define XS_WORDS (3 * XS_IW * ROWP)       // 9288 words = 37.2 KB
#define WS_WORDS (9 * C_OUT * ROWP)       // all 9 taps resident: 13824 words = 55.3 KB

// Scratch: conv output NHWC-flat [B*H_OUT*W_OUT, C_OUT] (67 MB)
__device__ __align__(256) float g_y[(size_t)B_ * H_OUT * W_OUT * C_OUT];
// Weights as fp16x2 words, [tap][co][ci/2] (ci pairs in natural order)
__device__ __align__(256) unsigned g_wH[9 * C_OUT * (C_IN / 2)];

// ---------------------------------------------------------------------------
// Kernel 0: weights (C_OUT,C_IN,3,3) -> fp16x2 [tap][co][ci/2]
// ---------------------------------------------------------------------------
__global__ void wt_kernel(const float* __restrict__ w) {
    int idx = blockIdx.x * blockDim.x + threadIdx.x;
    if (idx >= 9 * C_OUT * (C_IN / 2)) return;
    int pr  = idx % (C_IN / 2);
    int co  = (idx / (C_IN / 2)) % C_OUT;
    int tap = idx / ((C_IN / 2) * C_OUT);
    float w0 = w[(co * C_IN + 2 * pr) * 9 + tap];
    float w1 = w[(co * C_IN + 2 * pr + 1) * 9 + tap];
    __half2 h = __floats2half2_rn(w0, w1);
    g_wH[idx] = *(unsigned*)&h;
}

// ---------------------------------------------------------------------------
// Kernel 1: implicit-GEMM conv via mma.sync m16n8k16 fp16 (fp32 accum).
// Block: 256 thr (8 warps), tile M=128 pixels (one ho row) x N=128 co.
// Warp (wm 0..3, wn 0..1): 32 rows x 64 cols = 2 m16 x 8 n8 frags.
// Per ci-chunk: ONE cooperative fill of xs (input) and ws (all 9 taps'
// weights), then 9 taps x 16 MMAs from read-only smem with no syncs.
// 2 syncs per chunk, 8 per block (was 40).
// ---------------------------------------------------------------------------
__global__ __launch_bounds__(256, 2) void conv_kernel(
    const float* __restrict__ x,
    const float* __restrict__ bias)
{
    extern __shared__ unsigned smem[];
    unsigned* xs = smem;                  // [3][XS_IW][ROWP] fp16x2 words
    unsigned* ws = smem + XS_WORDS;       // [9][C_OUT][ROWP] fp16x2 words

    const int ho = blockIdx.x;
    const int b  = blockIdx.y;
    const int t  = threadIdx.x;
    const int lane = t & 31, warp = t >> 5;
    const int wm = warp >> 1;        // 0..3  (32 m-rows each)
    const int wn = warp & 1;         // 0..1  (64 co each)
    const int lq = lane >> 2;        // 0..7
    const int lr = lane & 3;         // 0..3

    float acc[2][8][4] = {};

    for (int cc = 0; cc < C_IN; cc += CICHUNK) {
        __syncthreads();   // xs/ws free (prev chunk's MMAs done)
        // ---- fill xs: [3 kh][258 iw] x 16 ci as 8 fp16x2 words, pitch ROWP
        for (int i = t; i < 3 * XS_IW * 2; i += 256) {
            int half = i / (3 * XS_IW);             // ci half: 0 -> ci 0..7, 1 -> 8..15
            int rem  = i % (3 * XS_IW);
            int r    = rem / XS_IW;
            int iw   = rem % XS_IW;
            int ih   = 2 * ho - 1 + r;
            int iwg  = iw - 1;
            unsigned u[4] = {0, 0, 0, 0};
            if (ih >= 0 && ih < H_IN && iwg >= 0 && iwg < W_IN) {
                const float* p = &x[(((size_t)(b * C_IN + cc + half * 8)) * H_IN + ih) * W_IN + iwg];
                #pragma unroll
                for (int j = 0; j < 4; j++) {
                    float f0 = p[(size_t)(2 * j) * H_IN * W_IN];
                    float f1 = p[(size_t)(2 * j + 1) * H_IN * W_IN];
                    __half2 h = __floats2half2_rn(f0, f1);
                    u[j] = *(unsigned*)&h;
                }
            }
            *(uint4*)&xs[(r * XS_IW + iw) * ROWP + half * 4] = make_uint4(u[0], u[1], u[2], u[3]);
        }
        // ---- fill ws: all 9 taps x 128 co x 16 ci (2304 uint4, 9 per thread)
        #pragma unroll
        for (int j = 0; j < 9; j++) {
            int idx  = t + 256 * j;          // 0..2303
            int half = idx & 1;
            int tc   = idx >> 1;             // tap*128 + co
            uint4 v = *(const uint4*)&g_wH[tc * (C_IN / 2) + (cc / 2) + half * 4];
            *(uint4*)&ws[tc * ROWP + half * 4] = v;
        }
        __syncthreads();   // xs + ws ready

        #pragma unroll
        for (int tap = 0; tap < 9; tap++) {
            const int kh = tap / 3, kw = tap % 3;
            // B fragments: col = wn*64 + j8*8 + lq; b0 = word[lr], b1 = word[lr+4]
            unsigned bf0[8], bf1[8];
            #pragma unroll
            for (int j8 = 0; j8 < 8; j8++) {
                const unsigned* br = &ws[(tap * C_OUT + wn * 64 + j8 * 8 + lq) * ROWP];
                bf0[j8] = br[lr];
                bf1[j8] = br[lr + 4];
            }
            #pragma unroll
            for (int i16 = 0; i16 < 2; i16++) {
                int m0 = wm * 32 + i16 * 16 + lq;
                const unsigned* xr0 = &xs[(kh * XS_IW + 2 * m0 + kw) * ROWP];
                const unsigned* xr1 = &xs[(kh * XS_IW + 2 * (m0 + 8) + kw) * ROWP];
                unsigned a0 = xr0[lr];
                unsigned a1 = xr1[lr];
                unsigned a2 = xr0[lr + 4];
                unsigned a3 = xr1[lr + 4];
                #pragma unroll
                for (int j8 = 0; j8 < 8; j8++) {
                    asm volatile(
                        "mma.sync.aligned.m16n8k16.row.col.f32.f16.f16.f32 "
                        "{%0,%1,%2,%3}, {%4,%5,%6,%7}, {%8,%9}, {%0,%1,%2,%3};"
                        : "+f"(acc[i16][j8][0]), "+f"(acc[i16][j8][1]),
                          "+f"(acc[i16][j8][2]), "+f"(acc[i16][j8][3])
                        : "r"(a0), "r"(a1), "r"(a2), "r"(a3),
                          "r"(bf0[j8]), "r"(bf1[j8]));
                }
            }
        }
    }

    // ---- epilogue: bias + ReLU -> g_y NHWC-flat
    size_t pixbase = ((size_t)(b * H_OUT + ho)) * W_OUT;
    #pragma unroll
    for (int i16 = 0; i16 < 2; i16++) {
        int m0 = wm * 32 + i16 * 16 + lq;
        #pragma unroll
        for (int j8 = 0; j8 < 8; j8++) {
            int co = wn * 64 + j8 * 8 + 2 * lr;
            float b0 = bias[co], b1 = bias[co + 1];
            float2 lo = make_float2(fmaxf(acc[i16][j8][0] + b0, 0.f),
                                    fmaxf(acc[i16][j8][1] + b1, 0.f));
            float2 hi = make_float2(fmaxf(acc[i16][j8][2] + b0, 0.f),
                                    fmaxf(acc[i16][j8][3] + b1, 0.f));
            *(float2*)&g_y[(pixbase + m0) * C_OUT + co]     = lo;
            *(float2*)&g_y[(pixbase + m0 + 8) * C_OUT + co] = hi;
        }
    }
}

// ---------------------------------------------------------------------------
// Kernel 2: fused gather + flattened double segment-max + additive fusion.
// One warp per 3D point; range = [a_ptr[v_ptr[n]], a_ptr[v_ptr[n+1]]).
// Post-ReLU values >= 0 => 0-init max == reference empty-segment semantics.
// ---------------------------------------------------------------------------
__global__ __launch_bounds__(256) void pool_fuse_kernel(
    const float* __restrict__ x3d,
    const int*   __restrict__ fm_idx,
    const int*   __restrict__ a_ptr,
    const int*   __restrict__ v_ptr,
    float*       __restrict__ out)
{
    int warp = (blockIdx.x * blockDim.x + threadIdx.x) >> 5;
    int lane = threadIdx.x & 31;
    if (warp >= N_PTS) return;

    int lo = a_ptr[v_ptr[warp]];
    int hi = a_ptr[v_ptr[warp + 1]];

    float4 acc = make_float4(0.0f, 0.0f, 0.0f, 0.0f);
    int i = lo;
    for (; i + 4 <= hi; i += 4) {
        int r0 = fm_idx[i + 0];
        int r1 = fm_idx[i + 1];
        int r2 = fm_idx[i + 2];
        int r3 = fm_idx[i + 3];
        float4 y0 = *(const float4*)&g_y[(size_t)r0 * C_OUT + lane * 4];
        float4 y1 = *(const float4*)&g_y[(size_t)r1 * C_OUT + lane * 4];
        float4 y2 = *(const float4*)&g_y[(size_t)r2 * C_OUT + lane * 4];
        float4 y3 = *(const float4*)&g_y[(size_t)r3 * C_OUT + lane * 4];
        acc.x = fmaxf(fmaxf(fmaxf(acc.x, y0.x), fmaxf(y1.x, y2.x)), y3.x);
        acc.y = fmaxf(fmaxf(fmaxf(acc.y, y0.y), fmaxf(y1.y, y2.y)), y3.y);
        acc.z = fmaxf(fmaxf(fmaxf(acc.z, y0.z), fmaxf(y1.z, y2.z)), y3.z);
        acc.w = fmaxf(fmaxf(fmaxf(acc.w, y0.w), fmaxf(y1.w, y2.w)), y3.w);
    }
    for (; i < hi; i++) {
        int r = fm_idx[i];
        float4 yv = *(const float4*)&g_y[(size_t)r * C_OUT + lane * 4];
        acc.x = fmaxf(acc.x, yv.x);
        acc.y = fmaxf(acc.y, yv.y);
        acc.z = fmaxf(acc.z, yv.z);
        acc.w = fmaxf(acc.w, yv.w);
    }

    float4 xv = *(const float4*)&x3d[(size_t)warp * C_OUT + lane * 4];
    *(float4*)&out[(size_t)warp * C_OUT + lane * 4] =
        make_float4(acc.x + xv.x, acc.y + xv.y, acc.z + xv.z, acc.w + xv.w);
}

// ---------------------------------------------------------------------------
// Launch: inputs x, w, b, x_3d, fm_idx, a_ptr, v_ptr
// ---------------------------------------------------------------------------
extern "C" void kernel_launch(void* const* d_in, const int* in_sizes, int n_in,
                              void* d_out, int out_size)
{
    const float* x      = (const float*)d_in[0];
    const float* w      = (const float*)d_in[1];
    const float* bias   = (const float*)d_in[2];
    const float* x3d    = (const float*)d_in[3];
    const int*   fm_idx = (const int*)d_in[4];
    const int*   a_ptr  = (const int*)d_in[5];
    const int*   v_ptr  = (const int*)d_in[6];
    float* out = (float*)d_out;

    wt_kernel<<<(9 * C_OUT * (C_IN / 2) + 255) / 256, 256>>>(w);

    const int smem_bytes = (XS_WORDS + WS_WORDS) * (int)sizeof(unsigned);   // 92.5 KB
    cudaFuncSetAttribute(conv_kernel, cudaFuncAttributeMaxDynamicSharedMemorySize, smem_bytes);
    dim3 cgrid(H_OUT, B_);
    conv_kernel<<<cgrid, 256, smem_bytes>>>(x, bias);

    int nblocks = (N_PTS + 7) / 8;
    pool_fuse_kernel<<<nblocks, 256>>>(x3d, fm_idx, a_ptr, v_ptr, out);
}

// round 11
// speedup vs baseline: 3.4258x; 1.1038x over previous
#include <cuda_runtime.h>
#include <cuda_fp16.h>
#include <cstdint>

// Problem constants
#define B_    8
#define C_IN  64
#define C_OUT 128
#define H_IN  256
#define W_IN  256
#define H_OUT 128
#define W_OUT 128
#define N_PTS 50000

#define CICHUNK 16       // ci per chunk (4 chunks); one k16 MMA per tap-chunk
#define XS_IW   258      // input cols: 2*128 + 2
#define ROWP    12       // words per row (8 fp16x2 + 4 pad): 12*lq+lr mod 32 injective
#define XS_WORDS (3 * XS_IW * ROWP)       // 9288 words = 37.2 KB
#define WS_WORDS (9 * C_OUT * ROWP)       // all 9 taps resident: 13824 words = 55.3 KB

// Scratch: conv output NHWC-flat [B*H_OUT*W_OUT, C_OUT] as fp16 (33.5 MB)
__device__ __align__(256) __half g_y[(size_t)B_ * H_OUT * W_OUT * C_OUT];
// Weights as fp16x2 words, [tap][co][ci/2] (ci pairs in natural order)
__device__ __align__(256) unsigned g_wH[9 * C_OUT * (C_IN / 2)];

// ---------------------------------------------------------------------------
// Kernel 0: weights (C_OUT,C_IN,3,3) -> fp16x2 [tap][co][ci/2]
// ---------------------------------------------------------------------------
__global__ void wt_kernel(const float* __restrict__ w) {
    int idx = blockIdx.x * blockDim.x + threadIdx.x;
    if (idx >= 9 * C_OUT * (C_IN / 2)) return;
    int pr  = idx % (C_IN / 2);
    int co  = (idx / (C_IN / 2)) % C_OUT;
    int tap = idx / ((C_IN / 2) * C_OUT);
    float w0 = w[(co * C_IN + 2 * pr) * 9 + tap];
    float w1 = w[(co * C_IN + 2 * pr + 1) * 9 + tap];
    __half2 h = __floats2half2_rn(w0, w1);
    g_wH[idx] = *(unsigned*)&h;
}

// ---------------------------------------------------------------------------
// Kernel 1: implicit-GEMM conv via mma.sync m16n8k16 fp16 (fp32 accum).
// Block: 256 thr (8 warps), tile M=128 pixels (one ho row) x N=128 co.
// Warp (wm 0..3, wn 0..1): 32 rows x 64 cols = 2 m16 x 8 n8 frags.
// Per ci-chunk: one cooperative fill of xs + ws (all 9 taps), then
// 9 taps x 16 MMAs from read-only smem. Epilogue stores fp16 half2.
// ---------------------------------------------------------------------------
__global__ __launch_bounds__(256, 2) void conv_kernel(
    const float* __restrict__ x,
    const float* __restrict__ bias)
{
    extern __shared__ unsigned smem[];
    unsigned* xs = smem;                  // [3][XS_IW][ROWP] fp16x2 words
    unsigned* ws = smem + XS_WORDS;       // [9][C_OUT][ROWP] fp16x2 words

    const int ho = blockIdx.x;
    const int b  = blockIdx.y;
    const int t  = threadIdx.x;
    const int lane = t & 31, warp = t >> 5;
    const int wm = warp >> 1;        // 0..3  (32 m-rows each)
    const int wn = warp & 1;         // 0..1  (64 co each)
    const int lq = lane >> 2;        // 0..7
    const int lr = lane & 3;         // 0..3

    float acc[2][8][4] = {};

    for (int cc = 0; cc < C_IN; cc += CICHUNK) {
        __syncthreads();   // xs/ws free (prev chunk's MMAs done)
        // ---- fill xs: [3 kh][258 iw] x 16 ci as 8 fp16x2 words, pitch ROWP
        for (int i = t; i < 3 * XS_IW * 2; i += 256) {
            int half = i / (3 * XS_IW);             // ci half: 0 -> ci 0..7, 1 -> 8..15
            int rem  = i % (3 * XS_IW);
            int r    = rem / XS_IW;
            int iw   = rem % XS_IW;
            int ih   = 2 * ho - 1 + r;
            int iwg  = iw - 1;
            unsigned u[4] = {0, 0, 0, 0};
            if (ih >= 0 && ih < H_IN && iwg >= 0 && iwg < W_IN) {
                const float* p = &x[(((size_t)(b * C_IN + cc + half * 8)) * H_IN + ih) * W_IN + iwg];
                #pragma unroll
                for (int j = 0; j < 4; j++) {
                    float f0 = p[(size_t)(2 * j) * H_IN * W_IN];
                    float f1 = p[(size_t)(2 * j + 1) * H_IN * W_IN];
                    __half2 h = __floats2half2_rn(f0, f1);
                    u[j] = *(unsigned*)&h;
                }
            }
            *(uint4*)&xs[(r * XS_IW + iw) * ROWP + half * 4] = make_uint4(u[0], u[1], u[2], u[3]);
        }
        // ---- fill ws: all 9 taps x 128 co x 16 ci (2304 uint4, 9 per thread)
        #pragma unroll
        for (int j = 0; j < 9; j++) {
            int idx  = t + 256 * j;          // 0..2303
            int half = idx & 1;
            int tc   = idx >> 1;             // tap*128 + co
            uint4 v = *(const uint4*)&g_wH[tc * (C_IN / 2) + (cc / 2) + half * 4];
            *(uint4*)&ws[tc * ROWP + half * 4] = v;
        }
        __syncthreads();   // xs + ws ready

        #pragma unroll
        for (int tap = 0; tap < 9; tap++) {
            const int kh = tap / 3, kw = tap % 3;
            unsigned bf0[8], bf1[8];
            #pragma unroll
            for (int j8 = 0; j8 < 8; j8++) {
                const unsigned* br = &ws[(tap * C_OUT + wn * 64 + j8 * 8 + lq) * ROWP];
                bf0[j8] = br[lr];
                bf1[j8] = br[lr + 4];
            }
            #pragma unroll
            for (int i16 = 0; i16 < 2; i16++) {
                int m0 = wm * 32 + i16 * 16 + lq;
                const unsigned* xr0 = &xs[(kh * XS_IW + 2 * m0 + kw) * ROWP];
                const unsigned* xr1 = &xs[(kh * XS_IW + 2 * (m0 + 8) + kw) * ROWP];
                unsigned a0 = xr0[lr];
                unsigned a1 = xr1[lr];
                unsigned a2 = xr0[lr + 4];
                unsigned a3 = xr1[lr + 4];
                #pragma unroll
                for (int j8 = 0; j8 < 8; j8++) {
                    asm volatile(
                        "mma.sync.aligned.m16n8k16.row.col.f32.f16.f16.f32 "
                        "{%0,%1,%2,%3}, {%4,%5,%6,%7}, {%8,%9}, {%0,%1,%2,%3};"
                        : "+f"(acc[i16][j8][0]), "+f"(acc[i16][j8][1]),
                          "+f"(acc[i16][j8][2]), "+f"(acc[i16][j8][3])
                        : "r"(a0), "r"(a1), "r"(a2), "r"(a3),
                          "r"(bf0[j8]), "r"(bf1[j8]));
                }
            }
        }
    }

    // ---- epilogue: bias + ReLU -> g_y NHWC-flat fp16 (half2 per co-pair)
    size_t pixbase = ((size_t)(b * H_OUT + ho)) * W_OUT;
    #pragma unroll
    for (int i16 = 0; i16 < 2; i16++) {
        int m0 = wm * 32 + i16 * 16 + lq;
        #pragma unroll
        for (int j8 = 0; j8 < 8; j8++) {
            int co = wn * 64 + j8 * 8 + 2 * lr;
            float b0 = bias[co], b1 = bias[co + 1];
            __half2 lo = __floats2half2_rn(fmaxf(acc[i16][j8][0] + b0, 0.f),
                                           fmaxf(acc[i16][j8][1] + b1, 0.f));
            __half2 hi = __floats2half2_rn(fmaxf(acc[i16][j8][2] + b0, 0.f),
                                           fmaxf(acc[i16][j8][3] + b1, 0.f));
            *(__half2*)&g_y[(pixbase + m0) * C_OUT + co]     = lo;
            *(__half2*)&g_y[(pixbase + m0 + 8) * C_OUT + co] = hi;
        }
    }
}

// ---------------------------------------------------------------------------
// Kernel 2: fused gather + flattened double segment-max + additive fusion.
// One warp per 3D point; range = [a_ptr[v_ptr[n]], a_ptr[v_ptr[n+1]]).
// Post-ReLU values >= 0 => 0-init max == reference empty-segment semantics.
// Lane handles 4 channels = 2 half2 (uint2 8B load); max in fp16 (exact),
// final add vs x3d in fp32.
// ---------------------------------------------------------------------------
__global__ __launch_bounds__(256) void pool_fuse_kernel(
    const float* __restrict__ x3d,
    const int*   __restrict__ fm_idx,
    const int*   __restrict__ a_ptr,
    const int*   __restrict__ v_ptr,
    float*       __restrict__ out)
{
    int warp = (blockIdx.x * blockDim.x + threadIdx.x) >> 5;
    int lane = threadIdx.x & 31;
    if (warp >= N_PTS) return;

    int lo = a_ptr[v_ptr[warp]];
    int hi = a_ptr[v_ptr[warp + 1]];

    __half2 acc0 = __float2half2_rn(0.f);
    __half2 acc1 = __float2half2_rn(0.f);
    int i = lo;
    for (; i + 4 <= hi; i += 4) {
        int r0 = fm_idx[i + 0];
        int r1 = fm_idx[i + 1];
        int r2 = fm_idx[i + 2];
        int r3 = fm_idx[i + 3];
        uint2 u0 = *(const uint2*)&g_y[(size_t)r0 * C_OUT + lane * 4];
        uint2 u1 = *(const uint2*)&g_y[(size_t)r1 * C_OUT + lane * 4];
        uint2 u2 = *(const uint2*)&g_y[(size_t)r2 * C_OUT + lane * 4];
        uint2 u3 = *(const uint2*)&g_y[(size_t)r3 * C_OUT + lane * 4];
        acc0 = __hmax2(__hmax2(acc0, *(__half2*)&u0.x),
                       __hmax2(*(__half2*)&u1.x,
                               __hmax2(*(__half2*)&u2.x, *(__half2*)&u3.x)));
        acc1 = __hmax2(__hmax2(acc1, *(__half2*)&u0.y),
                       __hmax2(*(__half2*)&u1.y,
                               __hmax2(*(__half2*)&u2.y, *(__half2*)&u3.y)));
    }
    for (; i < hi; i++) {
        int r = fm_idx[i];
        uint2 u = *(const uint2*)&g_y[(size_t)r * C_OUT + lane * 4];
        acc0 = __hmax2(acc0, *(__half2*)&u.x);
        acc1 = __hmax2(acc1, *(__half2*)&u.y);
    }

    float2 p0 = __half22float2(acc0);
    float2 p1 = __half22float2(acc1);
    float4 xv = *(const float4*)&x3d[(size_t)warp * C_OUT + lane * 4];
    *(float4*)&out[(size_t)warp * C_OUT + lane * 4] =
        make_float4(p0.x + xv.x, p0.y + xv.y, p1.x + xv.z, p1.y + xv.w);
}

// ---------------------------------------------------------------------------
// Launch: inputs x, w, b, x_3d, fm_idx, a_ptr, v_ptr
// ---------------------------------------------------------------------------
extern "C" void kernel_launch(void* const* d_in, const int* in_sizes, int n_in,
                              void* d_out, int out_size)
{
    const float* x      = (const float*)d_in[0];
    const float* w      = (const float*)d_in[1];
    const float* bias   = (const float*)d_in[2];
    const float* x3d    = (const float*)d_in[3];
    const int*   fm_idx = (const int*)d_in[4];
    const int*   a_ptr  = (const int*)d_in[5];
    const int*   v_ptr  = (const int*)d_in[6];
    float* out = (float*)d_out;

    wt_kernel<<<(9 * C_OUT * (C_IN / 2) + 255) / 256, 256>>>(w);

    const int smem_bytes = (XS_WORDS + WS_WORDS) * (int)sizeof(unsigned);   // 92.5 KB
    cudaFuncSetAttribute(conv_kernel, cudaFuncAttributeMaxDynamicSharedMemorySize, smem_bytes);
    dim3 cgrid(H_OUT, B_);
    conv_kernel<<<cgrid, 256, smem_bytes>>>(x, bias);

    int nblocks = (N_PTS + 7) / 8;
    pool_fuse_kernel<<<nblocks, 256>>>(x3d, fm_idx, a_ptr, v_ptr, out);
}